// round 7
// baseline (speedup 1.0000x reference)
#include <cuda_runtime.h>
#include <cstdint>
#include <math.h>

#define BLOCK 1024
#define GRID  36
#define CAP   16
#define FCAP  512

// shared-memory layout (floats)
#define OFF_X0    0        // 512    X buffer A: [e 0..255][h 0..1]
#define OFF_X1    512      // 512    X buffer B
#define OFF_SCAL  1024     // 768    per-stage scales [3][256]
#define OFF_CNT   1792     // 256    per-column correction count (int)
#define OFF_FCNT  2048     // 16     flat count (int, padded)
#define OFF_FPACK 2064     // 512    packed (d7*256+e8)<<11 | k (int)
#define OFF_FC6   2576     // 512    c6 per flat entry (int)
#define OFF_COLP7 3088     // 4096   correction d-index [256][CAP] (int)
#define OFF_COLCV 7184     // 12288  correction values [3][256][CAP]
#define OFF_RED   19472    // 8192   partials [16 dq][512]; FIRST reused as scan arrays
#define SMEM_FLOATS 27664
#define SMEM_BYTES (SMEM_FLOATS * 4)   // 110,656 B

// scan arrays alias the red region (dead before partials are written)
#define S5_OFF (OFF_RED + 0)
#define S7_OFF (OFF_RED + 2048)
#define S8_OFF (OFF_RED + 4096)
#define S6_OFF (OFF_RED + 6144)

extern __shared__ float smem[];

__device__ __forceinline__ void cp_async16(uint32_t saddr, const void* gptr) {
    asm volatile("cp.async.cg.shared.global [%0], [%1], 16;\n"
                 :: "r"(saddr), "l"(gptr));
}

__global__ void __launch_bounds__(BLOCK, 1)
chain_kernel(const float* __restrict__ p1, const float* __restrict__ p2,
             const float* __restrict__ p3, const float* __restrict__ p4,
             const int* __restrict__ p5, const int* __restrict__ p6,
             const int* __restrict__ p7, const int* __restrict__ p8,
             const float* __restrict__ p9, const float* __restrict__ p10,
             const float* __restrict__ p11, const float* __restrict__ p12,
             const float* __restrict__ p13, const float* __restrict__ p14,
             const float* __restrict__ p15, const float* __restrict__ p16,
             float* __restrict__ out, int K)
{
    const int tid = (int)threadIdx.x;
    const int b   = (int)blockIdx.x / 6;        // batch 0..5
    const int h0  = ((int)blockIdx.x % 6) * 2;  // head pair base

    float* X0     = smem + OFF_X0;
    float* X1     = smem + OFF_X1;
    float* scal   = smem + OFF_SCAL;
    float* colcv  = smem + OFF_COLCV;
    float* red    = smem + OFF_RED;
    int*   colcnt = (int*)(smem + OFF_CNT);
    int*   fcnt   = (int*)(smem + OFF_FCNT);
    int*   fpack  = (int*)(smem + OFF_FPACK);
    int*   fc6    = (int*)(smem + OFF_FC6);
    const int* s5 = (const int*)(smem + S5_OFF);
    const int* s7 = (const int*)(smem + S7_OFF);
    const int* s8 = (const int*)(smem + S8_OFF);
    const int* s6 = (const int*)(smem + S6_OFF);

    const int KC = (K < 2048) ? K : 2048;

    // ---- A: async copy of scatter index arrays into (future) red region ----
    {
        uint32_t sb = (uint32_t)__cvta_generic_to_shared(smem + OFF_RED);
        const int* src[4] = { p5, p7, p8, p6 };
        #pragma unroll
        for (int it = 0; it < 2; it++) {
            int idx = tid + it * BLOCK;
            int a = idx >> 9, c = idx & 511;
            if (c * 4 < KC)
                cp_async16(sb + (a * 2048 + c * 4) * 4, src[a] + c * 4);
        }
        asm volatile("cp.async.commit_group;\n" ::: "memory");
    }

    // ---- B: counters, X0 transpose-load, mod scales ----
    if (tid < 256) colcnt[tid] = 0;
    if (tid == 0)  fcnt[0] = 0;

    if (tid < 512) {    // X0[e*2+h] = p2[(h0+h), b, e]
        int d = tid >> 1, h = tid & 1;
        X0[tid] = p2[(h0 + h) * 1536 + b * 256 + d];
    }

    if (tid < 256) {
        float fr[3] = { p9[0],  p12[0], p15[0] };
        float ph[3] = { p10[0], p13[0], p16[0] };
        float t = (float)tid;
        #pragma unroll
        for (int s = 0; s < 3; s++) {
            float a  = t * 6.2831853071795864f;
            a = a * fr[s] + ph[s];
            float sv = sinf(a);
            float m  = sv * sv * 0.1f + 0.95f;
            scal[s * 256 + tid] = (s == 1) ? m : (1.0f / m);
        }
    }

    asm volatile("cp.async.wait_group 0;\n" ::: "memory");
    __syncthreads();

    // ---- C: scan (smem) -> flat list for this b ----
    #pragma unroll
    for (int it = 0; it < 2; it++) {
        int k = tid + it * BLOCK;
        if (k < KC && s5[k] == b) {
            int j = atomicAdd(fcnt, 1);
            if (j < FCAP) {
                fpack[j] = ((s7[k] * 256 + s8[k]) << 11) | k;
                fc6[j]   = s6[k];
            }
        }
    }
    __syncthreads();

    // ---- D: last-index-wins dedup -> per-column correction lists ----
    {
        int n = fcnt[0]; if (n > FCAP) n = FCAP;
        for (int i = tid; i < n; i += BLOCK) {
            int me  = fpack[i];
            int key = me >> 11;
            bool win = true;
            for (int j = 0; j < n; j++) {
                int oth = fpack[j];
                if ((oth >> 11) == key && oth > me) { win = false; break; }
            }
            if (win) {
                int d7 = key >> 8, e8 = key & 255, c6 = fc6[i];
                float pb = p1[b * 65536 + d7 * 256 + e8];
                int j = atomicAdd(&colcnt[e8], 1);
                if (j < CAP) {
                    ((int*)(smem + OFF_COLP7))[e8 * CAP + j] = d7;
                    colcv[0 * 4096 + e8 * CAP + j] = p4 [b * 256 + c6] - pb;
                    colcv[1 * 4096 + e8 * CAP + j] = p11[b * 256 + c6] - pb;
                    colcv[2 * 4096 + e8 * CAP + j] = p14[b * 256 + c6] - pb;
                }
            }
        }
    }
    __syncthreads();   // lists ready; red region free for partials

    // ---- 3-stage chain (no cross-CTA deps: h-partitioned) ----
    const int q  = tid & 63;        // e-quad: e = 4q..4q+3
    const int dq = tid >> 6;        // 0..15 : d-slice (16 d each)
    const int* colp7 = (const int*)(smem + OFF_COLP7);

    const float4* A1 = (const float4*)(p1 + b * 65536 + dq * 16 * 256 + q * 4);
    const float4* A3 = (const float4*)(p3 + b * 65536 + dq * 16 * 256 + q * 4);

    for (int s = 0; s < 3; s++) {
        const float* Xin  = (s & 1) ? X1 : X0;
        float*       Xout = (s & 1) ? X0 : X1;

        float acc[8];
        #pragma unroll
        for (int i = 0; i < 8; i++) acc[i] = 0.0f;

        const float2* Xd = (const float2*)(Xin + dq * 16 * 2);

        #pragma unroll
        for (int i = 0; i < 16; i++) {
            float4 a1 = A1[i * 64];
            float4 a3 = A3[i * 64];
            float4 m;
            m.x = fmaf(a3.x, 0.975f, a1.x);
            m.y = fmaf(a3.y, 0.975f, a1.y);
            m.z = fmaf(a3.z, 0.975f, a1.z);
            m.w = fmaf(a3.w, 0.975f, a1.w);
            float2 x = Xd[i];                    // broadcast (both heads)
            acc[0] += m.x * x.x;  acc[1] += m.x * x.y;
            acc[2] += m.y * x.x;  acc[3] += m.y * x.y;
            acc[4] += m.z * x.x;  acc[5] += m.z * x.y;
            acc[6] += m.w * x.x;  acc[7] += m.w * x.y;
        }

        // partials: red[dq][q*8 + e'*2 + h]
        *(float4*)&red[dq * 512 + q * 8]     = make_float4(acc[0], acc[1], acc[2], acc[3]);
        *(float4*)&red[dq * 512 + q * 8 + 4] = make_float4(acc[4], acc[5], acc[6], acc[7]);
        __syncthreads();

        // reduce 16 slices, apply corrections + scale, emit
        if (tid < 512) {
            int e = tid >> 1, h = tid & 1;
            float sum = 0.0f;
            #pragma unroll
            for (int d = 0; d < 16; d++) sum += red[d * 512 + tid];

            int n = colcnt[e]; if (n > CAP) n = CAP;
            for (int j = 0; j < n; j++) {
                int d7 = colp7[e * CAP + j];
                sum += Xin[d7 * 2 + h] * colcv[s * 4096 + e * CAP + j];
            }
            sum *= scal[s * 256 + e];
            if (s < 2) Xout[tid] = sum;
            else       out[(h0 + h) * 1536 + b * 256 + e] = sum;
        }
        __syncthreads();
    }
}

extern "C" void kernel_launch(void* const* d_in, const int* in_sizes, int n_in,
                              void* d_out, int out_size)
{
    (void)n_in; (void)out_size;
    cudaFuncSetAttribute(chain_kernel,
                         cudaFuncAttributeMaxDynamicSharedMemorySize, SMEM_BYTES);
    chain_kernel<<<GRID, BLOCK, SMEM_BYTES>>>(
        (const float*)d_in[0],  (const float*)d_in[1],
        (const float*)d_in[2],  (const float*)d_in[3],
        (const int*)  d_in[4],  (const int*)  d_in[5],
        (const int*)  d_in[6],  (const int*)  d_in[7],
        (const float*)d_in[8],  (const float*)d_in[9],
        (const float*)d_in[10], (const float*)d_in[11],
        (const float*)d_in[12], (const float*)d_in[13],
        (const float*)d_in[14], (const float*)d_in[15],
        (float*)d_out, in_sizes[4]);
}

// round 8
// speedup vs baseline: 1.8652x; 1.8652x over previous
#include <cuda_runtime.h>
#include <cooperative_groups.h>
#include <cstdint>
#include <math.h>

namespace cg = cooperative_groups;

#define BLOCK 512
#define CLUSTER 4
#define CAP 12

// shared-memory layout (floats)
#define OFF_X0    0        // 3072  X buffer A: [d][h] 256x12
#define OFF_X1    3072     // 3072  X buffer B
#define OFF_SCAL  6144     // 192   per-stage column scales [3][64]
#define OFF_CNT   6336     // 64    per-column bucket count (int)
#define OFF_COLK  6400     // 768   bucket packed (k<<8|d7) (int) [64][CAP]
#define OFF_COLC6 7168     // 768   bucket c6 (int) [64][CAP]
#define OFF_COLCV 7936     // 2304  correction values [3][64][CAP]
#define OFF_MC    10240    // 16384 M cache [256 d][64 e]
#define OFF_RED   26624    // 12288 partials [16][12][64]; FIRST reused as scan arrays
#define SMEM_FLOATS 38912
#define SMEM_BYTES (SMEM_FLOATS * 4)   // 155,648 B

// scan arrays alias the red region (dead before partials are written)
#define S5_OFF (OFF_RED + 0)
#define S7_OFF (OFF_RED + 2048)
#define S8_OFF (OFF_RED + 4096)
#define S6_OFF (OFF_RED + 6144)

extern __shared__ float smem[];

__device__ __forceinline__ void cp_async16(uint32_t saddr, const void* gptr) {
    asm volatile("cp.async.cg.shared.global [%0], [%1], 16;\n"
                 :: "r"(saddr), "l"(gptr));
}

__global__ void __cluster_dims__(CLUSTER, 1, 1) __launch_bounds__(BLOCK, 1)
chain_kernel(const float* __restrict__ p1, const float* __restrict__ p2,
             const float* __restrict__ p3, const float* __restrict__ p4,
             const int* __restrict__ p5, const int* __restrict__ p6,
             const int* __restrict__ p7, const int* __restrict__ p8,
             const float* __restrict__ p9, const float* __restrict__ p10,
             const float* __restrict__ p11, const float* __restrict__ p12,
             const float* __restrict__ p13, const float* __restrict__ p14,
             const float* __restrict__ p15, const float* __restrict__ p16,
             float* __restrict__ out, int K)
{
    cg::cluster_group cluster = cg::this_cluster();
    const int tid  = (int)threadIdx.x;
    const int rank = (int)cluster.block_rank();   // e-segment 0..3
    const int b    = (int)blockIdx.x >> 2;        // batch 0..5
    const int e0   = rank * 64;

    float* X0     = smem + OFF_X0;
    float* X1     = smem + OFF_X1;
    float* scal   = smem + OFF_SCAL;
    float* colcv  = smem + OFF_COLCV;
    float* Mc     = smem + OFF_MC;
    float* red    = smem + OFF_RED;
    int*   colcnt = (int*)(smem + OFF_CNT);
    int*   colk   = (int*)(smem + OFF_COLK);
    int*   colc6  = (int*)(smem + OFF_COLC6);
    const int* s5 = (const int*)(smem + S5_OFF);
    const int* s7 = (const int*)(smem + S7_OFF);
    const int* s8 = (const int*)(smem + S8_OFF);
    const int* s6 = (const int*)(smem + S6_OFF);

    const int KC = (K < 2048) ? K : 2048;

    // ---- A: async copy of scatter index arrays into (future) red region ----
    {
        uint32_t sb = (uint32_t)__cvta_generic_to_shared(smem + OFF_RED);
        const int* src[4] = { p5, p7, p8, p6 };
        #pragma unroll
        for (int it = 0; it < 4; it++) {
            int idx = tid + it * BLOCK;
            int a = idx >> 9, c = idx & 511;
            if (c * 4 < KC)
                cp_async16(sb + (a * 2048 + c * 4) * 4, src[a] + c * 4);
        }
        asm volatile("cp.async.commit_group;\n" ::: "memory");
    }

    // ---- B: counters, X0 transpose-load (coalesced per h-row), mod scales ----
    if (tid < 64) colcnt[tid] = 0;

    for (int i = tid; i < 3072; i += BLOCK) {     // 6 iters
        int h = i >> 8, d = i & 255;
        X0[d * 12 + h] = p2[h * 1536 + b * 256 + d];
    }

    if (tid < 64) {
        float fr[3] = { p9[0],  p12[0], p15[0] };
        float ph[3] = { p10[0], p13[0], p16[0] };
        float t = (float)(e0 + tid);
        #pragma unroll
        for (int s = 0; s < 3; s++) {
            float a  = t * 6.2831853071795864f;
            a = a * fr[s] + ph[s];
            float sv = sinf(a);
            float m  = sv * sv * 0.1f + 0.95f;
            scal[s * 64 + tid] = (s == 1) ? m : (1.0f / m);
        }
    }
    __syncthreads();    // X0 + counters visible

    // ---- thread mapping ----
    const int dch = tid >> 5;      // 0..15 : d-chunk (16 d each)
    const int ep  = tid & 31;      // 0..31 : e-column pair
    const int el2 = ep * 2;

    const float* P1 = p1 + b * 65536 + dch * 16 * 256 + e0 + el2;
    const float* P3 = p3 + b * 65536 + dch * 16 * 256 + e0 + el2;
    float* McB = Mc + dch * 16 * 64 + el2;

    float acc[24];
    #pragma unroll
    for (int i = 0; i < 24; i++) acc[i] = 0.0f;

    // ---- C: stage-0 dense mainloop from GLOBAL (hides cp.async); cache M ----
    {
        const float4* X4 = (const float4*)(X0 + dch * 16 * 12);
        #pragma unroll 4
        for (int i = 0; i < 16; i++) {
            float2 a = *(const float2*)(P1 + i * 256);
            float2 c = *(const float2*)(P3 + i * 256);
            float mx = fmaf(c.x, 0.975f, a.x);
            float my = fmaf(c.y, 0.975f, a.y);
            *(float2*)(McB + i * 64) = make_float2(mx, my);
            float4 xa = X4[i * 3 + 0];
            float4 xb = X4[i * 3 + 1];
            float4 xc = X4[i * 3 + 2];
            acc[0]  += xa.x * mx;  acc[1]  += xa.x * my;
            acc[2]  += xa.y * mx;  acc[3]  += xa.y * my;
            acc[4]  += xa.z * mx;  acc[5]  += xa.z * my;
            acc[6]  += xa.w * mx;  acc[7]  += xa.w * my;
            acc[8]  += xb.x * mx;  acc[9]  += xb.x * my;
            acc[10] += xb.y * mx;  acc[11] += xb.y * my;
            acc[12] += xb.z * mx;  acc[13] += xb.z * my;
            acc[14] += xb.w * mx;  acc[15] += xb.w * my;
            acc[16] += xc.x * mx;  acc[17] += xc.x * my;
            acc[18] += xc.y * mx;  acc[19] += xc.y * my;
            acc[20] += xc.z * mx;  acc[21] += xc.z * my;
            acc[22] += xc.w * mx;  acc[23] += xc.w * my;
        }
    }

    asm volatile("cp.async.wait_group 0;\n" ::: "memory");
    __syncthreads();    // scan arrays visible

    // ---- D: single-pass scan -> per-column buckets ----
    #pragma unroll
    for (int it = 0; it < 4; it++) {
        int k = tid + it * BLOCK;
        if (k < KC && s5[k] == b) {
            int e8 = s8[k];
            if ((e8 >> 6) == rank) {
                int el = e8 & 63;
                int j = atomicAdd(&colcnt[el], 1);
                if (j < CAP) {
                    colk[el * CAP + j]  = (k << 8) | s7[k];
                    colc6[el * CAP + j] = s6[k];
                }
            }
        }
    }
    __syncthreads();    // buckets built; scan arrays now dead

    // ---- E: winner resolution within buckets + correction values ----
    for (int o = tid; o < 64 * CAP; o += BLOCK) {   // 1.5 passes
        int el = o / CAP, j = o % CAP;
        int n = colcnt[el]; if (n > CAP) n = CAP;
        if (j < n) {
            int me = colk[el * CAP + j];
            bool win = true;
            for (int j2 = 0; j2 < n; j2++) {
                int oth = colk[el * CAP + j2];
                if (((oth ^ me) & 255) == 0 && oth > me) { win = false; break; }
            }
            if (win) {
                int d7 = me & 255, c6 = colc6[el * CAP + j];
                float pb = p1[b * 65536 + d7 * 256 + e0 + el];   // L2-hot
                colcv[0 * 768 + o] = p4 [b * 256 + c6] - pb;
                colcv[1 * 768 + o] = p11[b * 256 + c6] - pb;
                colcv[2 * 768 + o] = p14[b * 256 + c6] - pb;
            } else {
                colcv[0 * 768 + o] = 0.0f;
                colcv[1 * 768 + o] = 0.0f;
                colcv[2 * 768 + o] = 0.0f;
            }
        }
    }
    __syncthreads();    // corrections ready; red region free

    // ---- 3-stage chain (stage-0 acc already computed) ----
    for (int s = 0; s < 3; s++) {
        const float* Xin  = (s & 1) ? X1 : X0;
        float*       Xout = (s & 1) ? X0 : X1;

        if (s > 0) {
            #pragma unroll
            for (int i = 0; i < 24; i++) acc[i] = 0.0f;
            const float4* X4 = (const float4*)(Xin + dch * 16 * 12);
            #pragma unroll 4
            for (int i = 0; i < 16; i++) {
                float2 m = *(const float2*)(McB + i * 64);
                float mx = m.x, my = m.y;
                float4 xa = X4[i * 3 + 0];
                float4 xb = X4[i * 3 + 1];
                float4 xc = X4[i * 3 + 2];
                acc[0]  += xa.x * mx;  acc[1]  += xa.x * my;
                acc[2]  += xa.y * mx;  acc[3]  += xa.y * my;
                acc[4]  += xa.z * mx;  acc[5]  += xa.z * my;
                acc[6]  += xa.w * mx;  acc[7]  += xa.w * my;
                acc[8]  += xb.x * mx;  acc[9]  += xb.x * my;
                acc[10] += xb.y * mx;  acc[11] += xb.y * my;
                acc[12] += xb.z * mx;  acc[13] += xb.z * my;
                acc[14] += xb.w * mx;  acc[15] += xb.w * my;
                acc[16] += xc.x * mx;  acc[17] += xc.x * my;
                acc[18] += xc.y * mx;  acc[19] += xc.y * my;
                acc[20] += xc.z * mx;  acc[21] += xc.z * my;
                acc[22] += xc.w * mx;  acc[23] += xc.w * my;
            }
        }

        // write partials: red[dch][h][e]
        #pragma unroll
        for (int h = 0; h < 12; h++)
            *(float2*)&red[(dch * 12 + h) * 64 + el2] =
                make_float2(acc[2 * h], acc[2 * h + 1]);
        __syncthreads();

        // reduce 16 partials + per-column corrections + scale, emit
        for (int o = tid; o < 768; o += BLOCK) {
            int h = o >> 6, el = o & 63;
            float sum = 0.0f;
            #pragma unroll
            for (int dc = 0; dc < 16; dc++) sum += red[(dc * 12 + h) * 64 + el];

            int n = colcnt[el]; if (n > CAP) n = CAP;
            for (int j = 0; j < n; j++) {
                int d7 = colk[el * CAP + j] & 255;
                sum += Xin[d7 * 12 + h] * colcv[s * 768 + el * CAP + j];
            }
            sum *= scal[s * 64 + el];
            if (s < 2) Xout[(e0 + el) * 12 + h] = sum;
            else       out[h * 1536 + b * 256 + e0 + el] = sum;
        }

        if (s < 2) {
            cluster.sync();   // own X segment visible cluster-wide
            if (tid < 576 / 1) {  // pull 3 peer segments (192 float4 each)
                // loop handles 576 items with 512 threads
            }
            for (int i = tid; i < 576; i += BLOCK) {
                int pidx = i / 192;
                int off  = i % 192;
                unsigned sr = (unsigned)((rank + 1 + pidx) & 3);
                float* dst = Xout + sr * 768 + off * 4;
                const float* peer = cluster.map_shared_rank(dst, sr);
                *(float4*)dst = *(const float4*)peer;
            }
            __syncthreads();
        }
    }

    cluster.sync();   // no CTA exits while peers may still read its SMEM
}

extern "C" void kernel_launch(void* const* d_in, const int* in_sizes, int n_in,
                              void* d_out, int out_size)
{
    (void)n_in; (void)out_size;
    cudaFuncSetAttribute(chain_kernel,
                         cudaFuncAttributeMaxDynamicSharedMemorySize, SMEM_BYTES);
    chain_kernel<<<6 * CLUSTER, BLOCK, SMEM_BYTES>>>(
        (const float*)d_in[0],  (const float*)d_in[1],
        (const float*)d_in[2],  (const float*)d_in[3],
        (const int*)  d_in[4],  (const int*)  d_in[5],
        (const int*)  d_in[6],  (const int*)  d_in[7],
        (const float*)d_in[8],  (const float*)d_in[9],
        (const float*)d_in[10], (const float*)d_in[11],
        (const float*)d_in[12], (const float*)d_in[13],
        (const float*)d_in[14], (const float*)d_in[15],
        (float*)d_out, in_sizes[4]);
}

// round 10
// speedup vs baseline: 1.8910x; 1.0138x over previous
#include <cuda_runtime.h>
#include <cooperative_groups.h>
#include <cstdint>
#include <math.h>

namespace cg = cooperative_groups;

#define BLOCK 512
#define CLUSTER 8
#define CAP 12

// shared-memory layout (floats). Per CTA: 32 e-columns.
#define OFF_X0    0        // 3072  X buffer A: [d 0..255][h 0..11]
#define OFF_X1    3072     // 3072  X buffer B
#define OFF_SCAL  6144     // 96    per-stage column scales [3][32]
#define OFF_CNT   6240     // 32    per-column bucket count (int)
#define OFF_COLK  6272     // 384   bucket packed (k<<8|d7) (int) [32][CAP]
#define OFF_COLC6 6656     // 384   bucket c6 (int) [32][CAP]
#define OFF_COLCV 7040     // 1152  correction values [3][32][CAP]
#define OFF_MC    8192     // 8192  M cache [256 d][32 e]
#define OFF_RED   16384    // 6144  partials [16 dch][12 h][32 e]
#define OFF_SCAN  22528    // 8192  scan arrays p5/p7/p8/p6 (int)
#define SMEM_FLOATS 30720
#define SMEM_BYTES (SMEM_FLOATS * 4)   // 122,880 B

#define S5_OFF (OFF_SCAN + 0)
#define S7_OFF (OFF_SCAN + 2048)
#define S8_OFF (OFF_SCAN + 4096)
#define S6_OFF (OFF_SCAN + 6144)

extern __shared__ float smem[];

__device__ __forceinline__ void cp_async16(uint32_t saddr, const void* gptr) {
    asm volatile("cp.async.cg.shared.global [%0], [%1], 16;\n"
                 :: "r"(saddr), "l"(gptr));
}

__global__ void __cluster_dims__(CLUSTER, 1, 1) __launch_bounds__(BLOCK, 1)
chain_kernel(const float* __restrict__ p1, const float* __restrict__ p2,
             const float* __restrict__ p3, const float* __restrict__ p4,
             const int* __restrict__ p5, const int* __restrict__ p6,
             const int* __restrict__ p7, const int* __restrict__ p8,
             const float* __restrict__ p9, const float* __restrict__ p10,
             const float* __restrict__ p11, const float* __restrict__ p12,
             const float* __restrict__ p13, const float* __restrict__ p14,
             const float* __restrict__ p15, const float* __restrict__ p16,
             float* __restrict__ out, int K)
{
    cg::cluster_group cluster = cg::this_cluster();
    const int tid  = (int)threadIdx.x;
    const int rank = (int)cluster.block_rank();   // e-segment 0..7
    const int b    = (int)blockIdx.x >> 3;        // batch 0..5
    const int e0   = rank * 32;

    float* X0     = smem + OFF_X0;
    float* X1     = smem + OFF_X1;
    float* scal   = smem + OFF_SCAL;
    float* colcv  = smem + OFF_COLCV;
    float* Mc     = smem + OFF_MC;
    float* red    = smem + OFF_RED;
    int*   colcnt = (int*)(smem + OFF_CNT);
    int*   colk   = (int*)(smem + OFF_COLK);
    int*   colc6  = (int*)(smem + OFF_COLC6);
    const int* s5 = (const int*)(smem + S5_OFF);
    const int* s7 = (const int*)(smem + S7_OFF);
    const int* s8 = (const int*)(smem + S8_OFF);
    const int* s6 = (const int*)(smem + S6_OFF);

    const int KC = (K < 2048) ? K : 2048;

    // ---- A: async copy of scatter index arrays ----
    {
        uint32_t sb = (uint32_t)__cvta_generic_to_shared(smem + OFF_SCAN);
        const int* src[4] = { p5, p7, p8, p6 };
        #pragma unroll
        for (int it = 0; it < 4; it++) {
            int idx = tid + it * BLOCK;
            int a = idx >> 9, c = idx & 511;
            if (c * 4 < KC)
                cp_async16(sb + (a * 2048 + c * 4) * 4, src[a] + c * 4);
        }
        asm volatile("cp.async.commit_group;\n" ::: "memory");
    }

    // ---- B: counters, X0 transpose-load, mod scales ----
    if (tid < 32) colcnt[tid] = 0;

    for (int i = tid; i < 3072; i += BLOCK) {     // 6 iters
        int h = i >> 8, d = i & 255;
        X0[d * 12 + h] = p2[h * 1536 + b * 256 + d];
    }

    if (tid < 32) {
        float fr[3] = { p9[0],  p12[0], p15[0] };
        float ph[3] = { p10[0], p13[0], p16[0] };
        float t = (float)(e0 + tid);
        #pragma unroll
        for (int s = 0; s < 3; s++) {
            float a  = t * 6.2831853071795864f;
            a = a * fr[s] + ph[s];
            float sv = sinf(a);
            float m  = sv * sv * 0.1f + 0.95f;
            scal[s * 32 + tid] = (s == 1) ? m : (1.0f / m);
        }
    }
    __syncthreads();    // X0 + counters visible

    // ---- thread mapping: 16 d-chunks x 32 e-columns ----
    const int dch = tid >> 5;      // 0..15 (16 d each)
    const int el  = tid & 31;      // single e-column

    const float* P1 = p1 + b * 65536 + dch * 16 * 256 + e0 + el;
    const float* P3 = p3 + b * 65536 + dch * 16 * 256 + e0 + el;
    float* McB = Mc + dch * 16 * 32 + el;

    float acc[12];
    #pragma unroll
    for (int i = 0; i < 12; i++) acc[i] = 0.0f;

    // ---- C: stage-0 dense mainloop from GLOBAL (hides cp.async); cache M ----
    {
        const float4* X4 = (const float4*)(X0 + dch * 16 * 12);
        #pragma unroll 4
        for (int i = 0; i < 16; i++) {
            float a = P1[i * 256];
            float c = P3[i * 256];
            float m = fmaf(c, 0.975f, a);
            McB[i * 32] = m;
            float4 xa = X4[i * 3 + 0];
            float4 xb = X4[i * 3 + 1];
            float4 xc = X4[i * 3 + 2];
            acc[0]  += xa.x * m;  acc[1]  += xa.y * m;
            acc[2]  += xa.z * m;  acc[3]  += xa.w * m;
            acc[4]  += xb.x * m;  acc[5]  += xb.y * m;
            acc[6]  += xb.z * m;  acc[7]  += xb.w * m;
            acc[8]  += xc.x * m;  acc[9]  += xc.y * m;
            acc[10] += xc.z * m;  acc[11] += xc.w * m;
        }
    }

    asm volatile("cp.async.wait_group 0;\n" ::: "memory");
    __syncthreads();    // scan arrays visible

    // ---- D: single-pass scan -> per-column buckets ----
    #pragma unroll
    for (int it = 0; it < 4; it++) {
        int k = tid + it * BLOCK;
        if (k < KC && s5[k] == b) {
            int e8 = s8[k];
            if ((e8 >> 5) == rank) {
                int c = e8 & 31;
                int j = atomicAdd(&colcnt[c], 1);
                if (j < CAP) {
                    colk[c * CAP + j]  = (k << 8) | s7[k];
                    colc6[c * CAP + j] = s6[k];
                }
            }
        }
    }
    __syncthreads();

    // ---- E: winner resolution within buckets + correction values ----
    if (tid < 32 * CAP) {
        int c = tid / CAP, j = tid % CAP;
        int n = colcnt[c]; if (n > CAP) n = CAP;
        if (j < n) {
            int me = colk[c * CAP + j];
            bool win = true;
            for (int j2 = 0; j2 < n; j2++) {
                int oth = colk[c * CAP + j2];
                if (((oth ^ me) & 255) == 0 && oth > me) { win = false; break; }
            }
            if (win) {
                int d7 = me & 255, c6 = colc6[tid];
                float pb = p1[b * 65536 + d7 * 256 + e0 + c];   // L2-hot
                colcv[0 * 384 + tid] = p4 [b * 256 + c6] - pb;
                colcv[1 * 384 + tid] = p11[b * 256 + c6] - pb;
                colcv[2 * 384 + tid] = p14[b * 256 + c6] - pb;
            } else {
                colcv[0 * 384 + tid] = 0.0f;
                colcv[1 * 384 + tid] = 0.0f;
                colcv[2 * 384 + tid] = 0.0f;
            }
        }
    }
    __syncthreads();

    // ---- 3-stage chain (stage-0 acc already computed) ----
    for (int s = 0; s < 3; s++) {
        const float* Xin  = (s & 1) ? X1 : X0;
        float*       Xout = (s & 1) ? X0 : X1;

        if (s > 0) {
            #pragma unroll
            for (int i = 0; i < 12; i++) acc[i] = 0.0f;
            const float4* X4 = (const float4*)(Xin + dch * 16 * 12);
            #pragma unroll 4
            for (int i = 0; i < 16; i++) {
                float m = McB[i * 32];
                float4 xa = X4[i * 3 + 0];
                float4 xb = X4[i * 3 + 1];
                float4 xc = X4[i * 3 + 2];
                acc[0]  += xa.x * m;  acc[1]  += xa.y * m;
                acc[2]  += xa.z * m;  acc[3]  += xa.w * m;
                acc[4]  += xb.x * m;  acc[5]  += xb.y * m;
                acc[6]  += xb.z * m;  acc[7]  += xb.w * m;
                acc[8]  += xc.x * m;  acc[9]  += xc.y * m;
                acc[10] += xc.z * m;  acc[11] += xc.w * m;
            }
        }

        // write partials: red[dch][h][el]
        #pragma unroll
        for (int h = 0; h < 12; h++)
            red[(dch * 12 + h) * 32 + el] = acc[h];
        __syncthreads();

        // reduce 16 partials + corrections + scale; push result to all 8 CTAs
        if (tid < 384) {
            int h = tid >> 5, c = tid & 31;
            float sum = 0.0f;
            #pragma unroll
            for (int dc = 0; dc < 16; dc++) sum += red[(dc * 12 + h) * 32 + c];

            int n = colcnt[c]; if (n > CAP) n = CAP;
            for (int j = 0; j < n; j++) {
                int d7 = colk[c * CAP + j] & 255;
                sum += Xin[d7 * 12 + h] * colcv[s * 384 + c * CAP + j];
            }
            sum *= scal[s * 32 + c];

            if (s < 2) {
                float* dst = Xout + (e0 + c) * 12 + h;   // same offset in every CTA
                #pragma unroll
                for (int p = 0; p < CLUSTER; p++)
                    *cluster.map_shared_rank(dst, p) = sum;   // incl. self
            } else {
                out[h * 1536 + b * 256 + e0 + c] = sum;
            }
        }

        if (s < 2) cluster.sync();   // remote stores complete + full-CTA barrier
    }
}

extern "C" void kernel_launch(void* const* d_in, const int* in_sizes, int n_in,
                              void* d_out, int out_size)
{
    (void)n_in; (void)out_size;
    cudaFuncSetAttribute(chain_kernel,
                         cudaFuncAttributeMaxDynamicSharedMemorySize, SMEM_BYTES);
    chain_kernel<<<6 * CLUSTER, BLOCK, SMEM_BYTES>>>(
        (const float*)d_in[0],  (const float*)d_in[1],
        (const float*)d_in[2],  (const float*)d_in[3],
        (const int*)  d_in[4],  (const int*)  d_in[5],
        (const int*)  d_in[6],  (const int*)  d_in[7],
        (const float*)d_in[8],  (const float*)d_in[9],
        (const float*)d_in[10], (const float*)d_in[11],
        (const float*)d_in[12], (const float*)d_in[13],
        (const float*)d_in[14], (const float*)d_in[15],
        (float*)d_out, in_sizes[4]);
}